// round 2
// baseline (speedup 1.0000x reference)
#include <cuda_runtime.h>
#include <cuda_bf16.h>
#include <math.h>

// Problem constants
#define NN   1024
#define DD   128
#define DIN  137
#define NL   3
#define IPB  8      // i-rows per block in agg kernel
#define YD   4      // j-partitions per block

// ---------------- scratch (device globals; no allocation allowed) -----------
__device__ float g_h  [NN * DD];
__device__ float g_a  [NN * DD];
__device__ float g_cb [NN * DD];   // c + bm folded in
__device__ float g_agg[NN * DD];

// ---------------- exact GELU (erf-based, matches jax approximate=False) -----
__device__ __forceinline__ float gelu_exact(float x) {
    return 0.5f * x * (1.0f + erff(x * 0.70710678118654752f));
}

// ---------------- kernel 0: input projection h = nf @ Wp + bp ---------------
__global__ void k_proj(const float* __restrict__ nf,
                       const float* __restrict__ Wp,
                       const float* __restrict__ bp) {
    int i = blockIdx.x;
    int d = threadIdx.x;
    __shared__ float sh[DIN];
    for (int k = d; k < DIN; k += DD) sh[k] = nf[i * DIN + k];
    __syncthreads();
    float acc = bp[d];
    #pragma unroll 1
    for (int k = 0; k < DIN; ++k) acc = fmaf(sh[k], Wp[k * DD + d], acc);
    g_h[i * DD + d] = acc;
}

// ---------------- kernel 1: a = h@Wm[:D], cb = h@Wm[D:] + bm ----------------
__global__ void k_ac(const float* __restrict__ Wm,
                     const float* __restrict__ bm, int l) {
    int i = blockIdx.x;
    int d = threadIdx.x;
    __shared__ float sh[DD];
    sh[d] = g_h[i * DD + d];
    __syncthreads();
    const float* WA = Wm + (size_t)l * 2 * DD * DD;
    const float* WC = WA + DD * DD;
    float aa = 0.0f;
    float cc = bm[l * DD + d];
    #pragma unroll 4
    for (int k = 0; k < DD; ++k) {
        float hv = sh[k];
        aa = fmaf(hv, WA[k * DD + d], aa);
        cc = fmaf(hv, WC[k * DD + d], cc);
    }
    g_a [i * DD + d] = aa;
    g_cb[i * DD + d] = cc;
}

// ---------------- kernel 2: agg[i,d] = sum_j adj[i,j]*gelu(a[i,d]+cb[j,d]) --
__global__ __launch_bounds__(DD * YD, 1)
void k_agg(const float* __restrict__ adj) {
    int i0 = blockIdx.x * IPB;
    int d  = threadIdx.x;
    int ty = threadIdx.y;             // 0..YD-1, contiguous j-chunk per ty

    float av[IPB], acc[IPB];
    #pragma unroll
    for (int ii = 0; ii < IPB; ++ii) {
        av[ii]  = g_a[(i0 + ii) * DD + d];
        acc[ii] = 0.0f;
    }

    const int JC = NN / YD;           // 256 j per slice
    const int j0 = ty * JC;
    for (int j = j0; j < j0 + JC; j += 8) {
        float cv[8];
        #pragma unroll
        for (int u = 0; u < 8; ++u) cv[u] = g_cb[(j + u) * DD + d];
        #pragma unroll
        for (int ii = 0; ii < IPB; ++ii) {
            float4 ad0 = *reinterpret_cast<const float4*>(
                &adj[(size_t)(i0 + ii) * NN + j]);
            float4 ad1 = *reinterpret_cast<const float4*>(
                &adj[(size_t)(i0 + ii) * NN + j + 4]);
            acc[ii] = fmaf(ad0.x, gelu_exact(av[ii] + cv[0]), acc[ii]);
            acc[ii] = fmaf(ad0.y, gelu_exact(av[ii] + cv[1]), acc[ii]);
            acc[ii] = fmaf(ad0.z, gelu_exact(av[ii] + cv[2]), acc[ii]);
            acc[ii] = fmaf(ad0.w, gelu_exact(av[ii] + cv[3]), acc[ii]);
            acc[ii] = fmaf(ad1.x, gelu_exact(av[ii] + cv[4]), acc[ii]);
            acc[ii] = fmaf(ad1.y, gelu_exact(av[ii] + cv[5]), acc[ii]);
            acc[ii] = fmaf(ad1.z, gelu_exact(av[ii] + cv[6]), acc[ii]);
            acc[ii] = fmaf(ad1.w, gelu_exact(av[ii] + cv[7]), acc[ii]);
        }
    }

    __shared__ float red[YD][IPB][DD];
    #pragma unroll
    for (int ii = 0; ii < IPB; ++ii) red[ty][ii][d] = acc[ii];
    __syncthreads();
    // each ty finalizes IPB/YD rows
    for (int ii = ty * (IPB / YD); ii < (ty + 1) * (IPB / YD); ++ii) {
        float s = red[0][ii][d] + red[1][ii][d] + red[2][ii][d] + red[3][ii][d];
        g_agg[(i0 + ii) * DD + d] = s;
    }
}

// ---------------- kernel 3: update + residual + layernorm -------------------
__global__ void k_update(const float* __restrict__ Wu,
                         const float* __restrict__ bu,
                         const float* __restrict__ gamma,
                         const float* __restrict__ beta, int l) {
    int i = blockIdx.x;
    int d = threadIdx.x;
    __shared__ float hsh[DD], ash[DD];
    hsh[d] = g_h  [i * DD + d];
    ash[d] = g_agg[i * DD + d];
    __syncthreads();

    const float* W1 = Wu + (size_t)l * 2 * DD * DD;
    const float* W2 = W1 + DD * DD;
    float acc = bu[l * DD + d];
    #pragma unroll 4
    for (int k = 0; k < DD; ++k) {
        acc = fmaf(hsh[k], W1[k * DD + d], acc);
        acc = fmaf(ash[k], W2[k * DD + d], acc);
    }
    float x = gelu_exact(acc) + hsh[d];

    // layernorm across the 128 threads
    __shared__ float rs[4];
    float v = x;
    #pragma unroll
    for (int o = 16; o > 0; o >>= 1) v += __shfl_xor_sync(0xffffffffu, v, o);
    if ((d & 31) == 0) rs[d >> 5] = v;
    __syncthreads();
    float mean = (rs[0] + rs[1] + rs[2] + rs[3]) * (1.0f / DD);
    float xm = x - mean;
    float v2 = xm * xm;
    #pragma unroll
    for (int o = 16; o > 0; o >>= 1) v2 += __shfl_xor_sync(0xffffffffu, v2, o);
    __syncthreads();   // all mean-reads done before rs is reused
    if ((d & 31) == 0) rs[d >> 5] = v2;
    __syncthreads();
    float var = (rs[0] + rs[1] + rs[2] + rs[3]) * (1.0f / DD);
    float y = xm * rsqrtf(var + 1e-5f) * gamma[l * DD + d] + beta[l * DD + d];
    g_h[i * DD + d] = y;
}

// ---------------- kernel 4: output heads ------------------------------------
// out layout: threat[1024] | intent[1024*5] | action[1024*5] | h[1024*128]
__global__ void k_heads(const float* __restrict__ Wt,
                        const float* __restrict__ bt,
                        const float* __restrict__ Wi,
                        const float* __restrict__ bi,
                        const float* __restrict__ Wa,
                        const float* __restrict__ ba,
                        float* __restrict__ out) {
    int i = blockIdx.x;
    int d = threadIdx.x;
    __shared__ float hsh[DD];
    float hv = g_h[i * DD + d];
    hsh[d] = hv;
    __syncthreads();

    out[NN + NN * 5 + NN * 5 + i * DD + d] = hv;   // h copy

    if (d < 5) {
        float s = bi[d];
        #pragma unroll 8
        for (int k = 0; k < DD; ++k) s = fmaf(hsh[k], Wi[k * 5 + d], s);
        out[NN + i * 5 + d] = s;
        float s2 = ba[d];
        #pragma unroll 8
        for (int k = 0; k < DD; ++k) s2 = fmaf(hsh[k], Wa[k * 5 + d], s2);
        out[NN + NN * 5 + i * 5 + d] = s2;
    }
    if (d == 5) {
        float s = bt[0];
        #pragma unroll 8
        for (int k = 0; k < DD; ++k) s = fmaf(hsh[k], Wt[k], s);
        out[i] = 5.0f / (1.0f + expf(-s));
    }
}

// ---------------- launcher ---------------------------------------------------
extern "C" void kernel_launch(void* const* d_in, const int* in_sizes, int n_in,
                              void* d_out, int out_size) {
    const float* nf    = (const float*)d_in[0];   // node_feats (1024,137)
    const float* adj   = (const float*)d_in[1];   // adj (1024,1024)
    const float* Wp    = (const float*)d_in[2];   // (137,128)
    const float* bp    = (const float*)d_in[3];   // (128,)
    const float* Wm    = (const float*)d_in[4];   // (3,256,128)
    const float* bm    = (const float*)d_in[5];   // (3,128)
    const float* Wu    = (const float*)d_in[6];   // (3,256,128)
    const float* bu    = (const float*)d_in[7];   // (3,128)
    const float* gamma = (const float*)d_in[8];   // (3,128)
    const float* beta  = (const float*)d_in[9];   // (3,128)
    const float* Wt    = (const float*)d_in[10];  // (128,1)
    const float* bt    = (const float*)d_in[11];  // (1,)
    const float* Wi    = (const float*)d_in[12];  // (128,5)
    const float* bi    = (const float*)d_in[13];  // (5,)
    const float* Wa    = (const float*)d_in[14];  // (128,5)
    const float* ba    = (const float*)d_in[15];  // (5,)
    float* out = (float*)d_out;

    k_proj<<<NN, DD>>>(nf, Wp, bp);
    for (int l = 0; l < NL; ++l) {
        k_ac<<<NN, DD>>>(Wm, bm, l);
        dim3 blk(DD, YD);
        k_agg<<<NN / IPB, blk>>>(adj);
        k_update<<<NN, DD>>>(Wu, bu, gamma, beta, l);
    }
    k_heads<<<NN, DD>>>(Wt, bt, Wi, bi, Wa, ba, out);
}

// round 3
// speedup vs baseline: 1.5057x; 1.5057x over previous
#include <cuda_runtime.h>
#include <cuda_bf16.h>
#include <math.h>

// Problem constants
#define NN   1024
#define DD   128
#define DIN  137
#define NL   3
#define IPB  8      // i-rows per agg block
#define YD   8      // j-partitions per agg block
#define ACR  4      // rows per block in small GEMM kernels

typedef unsigned long long ull;

// ---------------- scratch (device globals; no allocation allowed) -----------
__device__ float g_h  [NN * DD];
__device__ float g_a  [NN * DD];   // pre-scaled by 1/sqrt(2)
__device__ float g_cb [NN * DD];   // (c + bm) pre-scaled by 1/sqrt(2)
__device__ float g_agg[NN * DD];

// ---------------- packed f32x2 helpers --------------------------------------
__device__ __forceinline__ ull pk2(float a, float b) {
    ull r; asm("mov.b64 %0, {%1,%2};" : "=l"(r) : "f"(a), "f"(b)); return r;
}
__device__ __forceinline__ ull add2(ull a, ull b) {
    ull r; asm("add.rn.f32x2 %0, %1, %2;" : "=l"(r) : "l"(a), "l"(b)); return r;
}
__device__ __forceinline__ ull mul2(ull a, ull b) {
    ull r; asm("mul.rn.f32x2 %0, %1, %2;" : "=l"(r) : "l"(a), "l"(b)); return r;
}
__device__ __forceinline__ ull fma2(ull a, ull b, ull c) {
    ull r; asm("fma.rn.f32x2 %0, %1, %2, %3;" : "=l"(r) : "l"(a), "l"(b), "l"(c)); return r;
}

// Taylor coefficients of erf(z) = z * P(z^2):  c_n = (2/sqrt(pi)) * (-1)^n / (n! (2n+1))
#define EC0   1.1283791671e+0f
#define EC1  -3.7612638903e-1f
#define EC2   1.1283791671e-1f
#define EC3  -2.6866170645e-2f
#define EC4   5.2239776254e-3f
#define EC5  -8.5483270234e-4f
#define EC6   1.2055332982e-4f
#define EC7  -1.4925650358e-5f
#define EC8   1.6462114365e-6f
#define EC9  -1.6365844691e-7f
#define EC10  1.4807192816e-8f
#define EC11 -1.2290555302e-9f

// ---------------- exact GELU (erf-based) for the cold kernels ----------------
__device__ __forceinline__ float gelu_exact(float x) {
    return 0.5f * x * (1.0f + erff(x * 0.70710678118654752f));
}

// ---------------- kernel 0: input projection h = nf @ Wp + bp ---------------
__global__ void k_proj(const float* __restrict__ nf,
                       const float* __restrict__ Wp,
                       const float* __restrict__ bp) {
    int i0 = blockIdx.x * ACR;
    int d  = threadIdx.x;
    __shared__ float sh[ACR][DIN];
    #pragma unroll
    for (int r = 0; r < ACR; ++r)
        for (int k = d; k < DIN; k += DD) sh[r][k] = nf[(i0 + r) * DIN + k];
    __syncthreads();
    float acc[ACR];
    float b = bp[d];
    #pragma unroll
    for (int r = 0; r < ACR; ++r) acc[r] = b;
    #pragma unroll 4
    for (int k = 0; k < DIN; ++k) {
        float w = Wp[k * DD + d];
        #pragma unroll
        for (int r = 0; r < ACR; ++r) acc[r] = fmaf(sh[r][k], w, acc[r]);
    }
    #pragma unroll
    for (int r = 0; r < ACR; ++r) g_h[(i0 + r) * DD + d] = acc[r];
}

// ---- kernel 1: a = (h@Wm[:D])/sqrt2, cb = (h@Wm[D:]+bm)/sqrt2 --------------
__global__ void k_ac(const float* __restrict__ Wm,
                     const float* __restrict__ bm, int l) {
    int i0 = blockIdx.x * ACR;
    int d  = threadIdx.x;
    __shared__ float sh[ACR][DD];
    #pragma unroll
    for (int r = 0; r < ACR; ++r) sh[r][d] = g_h[(i0 + r) * DD + d];
    __syncthreads();
    const float* WA = Wm + (size_t)l * 2 * DD * DD;
    const float* WC = WA + DD * DD;
    float aa[ACR] = {0.f, 0.f, 0.f, 0.f};
    float cc[ACR] = {0.f, 0.f, 0.f, 0.f};
    #pragma unroll 4
    for (int k = 0; k < DD; ++k) {
        float wa = WA[k * DD + d];
        float wc = WC[k * DD + d];
        #pragma unroll
        for (int r = 0; r < ACR; ++r) {
            float hv = sh[r][k];
            aa[r] = fmaf(hv, wa, aa[r]);
            cc[r] = fmaf(hv, wc, cc[r]);
        }
    }
    const float S = 0.70710678118654752f;
    float bmv = bm[l * DD + d];
    #pragma unroll
    for (int r = 0; r < ACR; ++r) {
        g_a [(i0 + r) * DD + d] = aa[r] * S;
        g_cb[(i0 + r) * DD + d] = (cc[r] + bmv) * S;
    }
}

// ---------------- kernel 2: agg[i,d] = sum_j adj[i,j]*gelu(a[i,d]+c[j,d]) ---
// packed f32x2: thread handles d-pair (2t, 2t+1). z = a' + c' (already /sqrt2)
// erf(z)=z*P(z^2); gelu = hx*(1+erf) with hx = 0.5*x = z*0.7071
__global__ __launch_bounds__(64 * YD, 1)
void k_agg(const float* __restrict__ adj) {
    int i0 = blockIdx.x * IPB;
    int t  = threadIdx.x;            // 0..63 d-pair index
    int ty = threadIdx.y;            // 0..YD-1
    int d2 = t * 2;

    // packed constants (warp-uniform)
    ull K0  = pk2(EC0 , EC0 ), K1  = pk2(EC1 , EC1 ), K2  = pk2(EC2 , EC2 );
    ull K3  = pk2(EC3 , EC3 ), K4  = pk2(EC4 , EC4 ), K5  = pk2(EC5 , EC5 );
    ull K6  = pk2(EC6 , EC6 ), K7  = pk2(EC7 , EC7 ), K8  = pk2(EC8 , EC8 );
    ull K9  = pk2(EC9 , EC9 ), K10 = pk2(EC10, EC10), K11 = pk2(EC11, EC11);
    ull KH  = pk2(0.70710678118654752f, 0.70710678118654752f);

    ull av2[IPB], acc[IPB];
    #pragma unroll
    for (int ii = 0; ii < IPB; ++ii) {
        av2[ii] = *reinterpret_cast<const ull*>(&g_a[(i0 + ii) * DD + d2]);
        acc[ii] = 0ull;   // bit pattern of (0.f,0.f)
    }

#define EVAL(ACC, AV, CV, AD) do {                                  \
        ull z  = add2((AV), (CV));                                  \
        ull q  = mul2(z, z);                                        \
        ull p  = K11;                                               \
        p = fma2(p, q, K10); p = fma2(p, q, K9); p = fma2(p, q, K8);\
        p = fma2(p, q, K7);  p = fma2(p, q, K6); p = fma2(p, q, K5);\
        p = fma2(p, q, K4);  p = fma2(p, q, K3); p = fma2(p, q, K2);\
        p = fma2(p, q, K1);  p = fma2(p, q, K0);                    \
        ull e  = mul2(p, z);                                        \
        ull hx = mul2(z, KH);                                       \
        ull g  = fma2(hx, e, hx);                                   \
        ull a2 = pk2((AD), (AD));                                   \
        (ACC)  = fma2(a2, g, (ACC));                                \
    } while (0)

    const int JC = NN / YD;          // 128 j per slice
    const int j0 = ty * JC;
    for (int j = j0; j < j0 + JC; j += 4) {
        ull cv2[4];
        #pragma unroll
        for (int u = 0; u < 4; ++u)
            cv2[u] = *reinterpret_cast<const ull*>(&g_cb[(j + u) * DD + d2]);
        #pragma unroll
        for (int ii = 0; ii < IPB; ++ii) {
            float4 ad = *reinterpret_cast<const float4*>(
                &adj[(size_t)(i0 + ii) * NN + j]);
            EVAL(acc[ii], av2[ii], cv2[0], ad.x);
            EVAL(acc[ii], av2[ii], cv2[1], ad.y);
            EVAL(acc[ii], av2[ii], cv2[2], ad.z);
            EVAL(acc[ii], av2[ii], cv2[3], ad.w);
        }
    }
#undef EVAL

    __shared__ ull red[YD][IPB][64];
    #pragma unroll
    for (int ii = 0; ii < IPB; ++ii) red[ty][ii][t] = acc[ii];
    __syncthreads();
    // each ty finalizes one row (IPB == YD)
    {
        int ii = ty;
        ull s = red[0][ii][t];
        #pragma unroll
        for (int p = 1; p < YD; ++p) s = add2(s, red[p][ii][t]);
        *reinterpret_cast<ull*>(&g_agg[(i0 + ii) * DD + d2]) = s;
    }
}

// ---------------- kernel 3: update + residual + layernorm -------------------
__global__ void k_update(const float* __restrict__ Wu,
                         const float* __restrict__ bu,
                         const float* __restrict__ gamma,
                         const float* __restrict__ beta, int l) {
    int i0 = blockIdx.x * ACR;
    int d  = threadIdx.x;
    __shared__ float hsh[ACR][DD], ash[ACR][DD];
    #pragma unroll
    for (int r = 0; r < ACR; ++r) {
        hsh[r][d] = g_h  [(i0 + r) * DD + d];
        ash[r][d] = g_agg[(i0 + r) * DD + d];
    }
    __syncthreads();

    const float* W1 = Wu + (size_t)l * 2 * DD * DD;
    const float* W2 = W1 + DD * DD;
    float acc[ACR];
    float b = bu[l * DD + d];
    #pragma unroll
    for (int r = 0; r < ACR; ++r) acc[r] = b;
    #pragma unroll 4
    for (int k = 0; k < DD; ++k) {
        float w1 = W1[k * DD + d];
        float w2 = W2[k * DD + d];
        #pragma unroll
        for (int r = 0; r < ACR; ++r) {
            acc[r] = fmaf(hsh[r][k], w1, acc[r]);
            acc[r] = fmaf(ash[r][k], w2, acc[r]);
        }
    }

    float x[ACR];
    #pragma unroll
    for (int r = 0; r < ACR; ++r) x[r] = gelu_exact(acc[r]) + hsh[r][d];

    // layernorm per row across the 128 threads
    __shared__ float rs_m[ACR][4], rs_v[ACR][4];
    #pragma unroll
    for (int r = 0; r < ACR; ++r) {
        float v = x[r];
        #pragma unroll
        for (int o = 16; o > 0; o >>= 1) v += __shfl_xor_sync(0xffffffffu, v, o);
        if ((d & 31) == 0) rs_m[r][d >> 5] = v;
    }
    __syncthreads();
    float mean[ACR];
    #pragma unroll
    for (int r = 0; r < ACR; ++r)
        mean[r] = (rs_m[r][0] + rs_m[r][1] + rs_m[r][2] + rs_m[r][3]) * (1.0f / DD);
    #pragma unroll
    for (int r = 0; r < ACR; ++r) {
        float xm = x[r] - mean[r];
        float v2 = xm * xm;
        #pragma unroll
        for (int o = 16; o > 0; o >>= 1) v2 += __shfl_xor_sync(0xffffffffu, v2, o);
        if ((d & 31) == 0) rs_v[r][d >> 5] = v2;
    }
    __syncthreads();
    float gmv = gamma[l * DD + d];
    float btv = beta [l * DD + d];
    #pragma unroll
    for (int r = 0; r < ACR; ++r) {
        float var = (rs_v[r][0] + rs_v[r][1] + rs_v[r][2] + rs_v[r][3]) * (1.0f / DD);
        float y = (x[r] - mean[r]) * rsqrtf(var + 1e-5f) * gmv + btv;
        g_h[(i0 + r) * DD + d] = y;
    }
}

// ---------------- kernel 4: output heads ------------------------------------
// out layout: threat[1024] | intent[1024*5] | action[1024*5] | h[1024*128]
__global__ void k_heads(const float* __restrict__ Wt,
                        const float* __restrict__ bt,
                        const float* __restrict__ Wi,
                        const float* __restrict__ bi,
                        const float* __restrict__ Wa,
                        const float* __restrict__ ba,
                        float* __restrict__ out) {
    int i = blockIdx.x;
    int d = threadIdx.x;
    __shared__ float hsh[DD];
    float hv = g_h[i * DD + d];
    hsh[d] = hv;
    __syncthreads();

    out[NN + NN * 5 + NN * 5 + i * DD + d] = hv;   // h copy

    if (d < 5) {
        float s = bi[d];
        #pragma unroll 8
        for (int k = 0; k < DD; ++k) s = fmaf(hsh[k], Wi[k * 5 + d], s);
        out[NN + i * 5 + d] = s;
        float s2 = ba[d];
        #pragma unroll 8
        for (int k = 0; k < DD; ++k) s2 = fmaf(hsh[k], Wa[k * 5 + d], s2);
        out[NN + NN * 5 + i * 5 + d] = s2;
    }
    if (d == 5) {
        float s = bt[0];
        #pragma unroll 8
        for (int k = 0; k < DD; ++k) s = fmaf(hsh[k], Wt[k], s);
        out[i] = 5.0f / (1.0f + expf(-s));
    }
}

// ---------------- launcher ---------------------------------------------------
extern "C" void kernel_launch(void* const* d_in, const int* in_sizes, int n_in,
                              void* d_out, int out_size) {
    const float* nf    = (const float*)d_in[0];
    const float* adj   = (const float*)d_in[1];
    const float* Wp    = (const float*)d_in[2];
    const float* bp    = (const float*)d_in[3];
    const float* Wm    = (const float*)d_in[4];
    const float* bm    = (const float*)d_in[5];
    const float* Wu    = (const float*)d_in[6];
    const float* bu    = (const float*)d_in[7];
    const float* gamma = (const float*)d_in[8];
    const float* beta  = (const float*)d_in[9];
    const float* Wt    = (const float*)d_in[10];
    const float* bt    = (const float*)d_in[11];
    const float* Wi    = (const float*)d_in[12];
    const float* bi    = (const float*)d_in[13];
    const float* Wa    = (const float*)d_in[14];
    const float* ba    = (const float*)d_in[15];
    float* out = (float*)d_out;

    k_proj<<<NN / ACR, DD>>>(nf, Wp, bp);
    for (int l = 0; l < NL; ++l) {
        k_ac<<<NN / ACR, DD>>>(Wm, bm, l);
        dim3 blk(64, YD);
        k_agg<<<NN / IPB, blk>>>(adj);
        k_update<<<NN / ACR, DD>>>(Wu, bu, gamma, beta, l);
    }
    k_heads<<<NN, DD>>>(Wt, bt, Wi, bi, Wa, ba, out);
}

// round 4
// speedup vs baseline: 2.4124x; 1.6022x over previous
#include <cuda_runtime.h>
#include <cuda_bf16.h>
#include <math.h>

// Problem constants
#define NN   1024
#define DD   128
#define DIN  137
#define NL   3
#define IPB  7      // i-rows per agg block (147 blocks = 1 wave on 148 SMs)
#define YD   8      // j-partitions per agg block
#define ACR  4      // rows per block (and k-slices) in fused GEMM kernels

typedef unsigned long long ull;

// ---------------- scratch (device globals; no allocation allowed) -----------
__device__ float g_h  [NN * DD];
__device__ float g_a  [NN * DD];   // pre-scaled by 1/sqrt(2)
__device__ float g_cb [NN * DD];   // (c + bm) pre-scaled by 1/sqrt(2)
__device__ float g_agg[NN * DD];

// ---------------- packed f32x2 helpers --------------------------------------
__device__ __forceinline__ ull pk2(float a, float b) {
    ull r; asm("mov.b64 %0, {%1,%2};" : "=l"(r) : "f"(a), "f"(b)); return r;
}
__device__ __forceinline__ ull add2(ull a, ull b) {
    ull r; asm("add.rn.f32x2 %0, %1, %2;" : "=l"(r) : "l"(a), "l"(b)); return r;
}
__device__ __forceinline__ ull mul2(ull a, ull b) {
    ull r; asm("mul.rn.f32x2 %0, %1, %2;" : "=l"(r) : "l"(a), "l"(b)); return r;
}
__device__ __forceinline__ ull fma2(ull a, ull b, ull c) {
    ull r; asm("fma.rn.f32x2 %0, %1, %2, %3;" : "=l"(r) : "l"(a), "l"(b), "l"(c)); return r;
}

// Taylor coeffs of erf(z)=z*P(z^2), pre-scaled by 1/sqrt(2):
// gelu(x) = z*(C + z*Ptilde(z^2)),  z = x/sqrt(2),  C = 1/sqrt(2)
#define EC0S  7.9788456080e-1f
#define EC1S -2.6596152027e-1f
#define EC2S  7.9788456080e-2f
#define EC3S -1.8997270260e-2f
#define EC4S  3.6939104237e-3f
#define EC5S -6.0446590722e-4f
#define EC6S  8.5244784915e-5f
#define EC7S -1.0554088026e-5f
#define EC8S  1.1640490008e-6f
#define CSQ2  7.0710678119e-1f

// ---------------- exact GELU (erf-based) for the cold path -------------------
__device__ __forceinline__ float gelu_exact(float x) {
    return 0.5f * x * (1.0f + erff(x * 0.70710678118654752f));
}

// ============ kernel A: proj + a/c of layer 0 (fused, k-split) ==============
__global__ void k_proj_ac(const float* __restrict__ nf,
                          const float* __restrict__ Wp,
                          const float* __restrict__ bp,
                          const float* __restrict__ Wm,
                          const float* __restrict__ bm) {
    int i0 = blockIdx.x * ACR;
    int d  = threadIdx.x;      // 0..127
    int ty = threadIdx.y;      // 0..3 k-slice / row id
    int tid = ty * DD + d;

    __shared__ float sh[ACR][DIN + 3];
    __shared__ float hn[ACR][DD];
    __shared__ float red[ACR][ACR][DD];   // [slice][row][d]

    for (int e = tid; e < ACR * DIN; e += ACR * DD) {
        int r = e / DIN, c = e % DIN;
        sh[r][c] = nf[(i0 + r) * DIN + c];
    }
    __syncthreads();

    // ---- proj GEMM, k-split over DIN ----
    {
        int k0 = (ty * DIN) / ACR, k1 = ((ty + 1) * DIN) / ACR;
        float acc[ACR] = {0.f, 0.f, 0.f, 0.f};
        for (int k = k0; k < k1; ++k) {
            float w = Wp[k * DD + d];
            #pragma unroll
            for (int r = 0; r < ACR; ++r) acc[r] = fmaf(sh[r][k], w, acc[r]);
        }
        #pragma unroll
        for (int r = 0; r < ACR; ++r) red[ty][r][d] = acc[r];
    }
    __syncthreads();
    {
        float h = bp[d] + red[0][ty][d] + red[1][ty][d] + red[2][ty][d] + red[3][ty][d];
        g_h[(i0 + ty) * DD + d] = h;
        hn[ty][d] = h;
    }
    __syncthreads();

    // ---- a/c GEMM for layer 0, k-split (32 per slice) ----
    const float* WA = Wm;               // layer 0
    const float* WC = Wm + DD * DD;
    float aa[ACR] = {0.f, 0.f, 0.f, 0.f};
    float cc[ACR] = {0.f, 0.f, 0.f, 0.f};
    int k0 = ty * 32;
    #pragma unroll 8
    for (int kk = 0; kk < 32; ++kk) {
        int k = k0 + kk;
        float wa = WA[k * DD + d];
        float wc = WC[k * DD + d];
        #pragma unroll
        for (int r = 0; r < ACR; ++r) {
            float hv = hn[r][k];
            aa[r] = fmaf(hv, wa, aa[r]);
            cc[r] = fmaf(hv, wc, cc[r]);
        }
    }
    #pragma unroll
    for (int r = 0; r < ACR; ++r) red[ty][r][d] = aa[r];
    __syncthreads();
    g_a[(i0 + ty) * DD + d] =
        (red[0][ty][d] + red[1][ty][d] + red[2][ty][d] + red[3][ty][d]) * CSQ2;
    __syncthreads();
    #pragma unroll
    for (int r = 0; r < ACR; ++r) red[ty][r][d] = cc[r];
    __syncthreads();
    g_cb[(i0 + ty) * DD + d] =
        (red[0][ty][d] + red[1][ty][d] + red[2][ty][d] + red[3][ty][d] + bm[d]) * CSQ2;
}

// ============ kernel B: agg (packed f32x2, 9-term scaled poly) ==============
__global__ __launch_bounds__(64 * YD, 1)
void k_agg(const float* __restrict__ adj) {
    int i0 = blockIdx.x * IPB;
    int rows = NN - i0; if (rows > IPB) rows = IPB;
    int t  = threadIdx.x;            // 0..63 d-pair index
    int ty = threadIdx.y;            // 0..YD-1
    int d2 = t * 2;

    ull K0 = pk2(EC0S, EC0S), K1 = pk2(EC1S, EC1S), K2 = pk2(EC2S, EC2S);
    ull K3 = pk2(EC3S, EC3S), K4 = pk2(EC4S, EC4S), K5 = pk2(EC5S, EC5S);
    ull K6 = pk2(EC6S, EC6S), K7 = pk2(EC7S, EC7S), K8 = pk2(EC8S, EC8S);
    ull KC = pk2(CSQ2, CSQ2);

    ull av2[IPB], acc[IPB];
    #pragma unroll
    for (int ii = 0; ii < IPB; ++ii) {
        av2[ii] = (ii < rows)
            ? *reinterpret_cast<const ull*>(&g_a[(i0 + ii) * DD + d2]) : 0ull;
        acc[ii] = 0ull;
    }

#define EVAL(ACC, AV, CV, AD) do {                                  \
        ull z = add2((AV), (CV));                                   \
        ull q = mul2(z, z);                                         \
        ull p = K8;                                                 \
        p = fma2(p, q, K7); p = fma2(p, q, K6); p = fma2(p, q, K5); \
        p = fma2(p, q, K4); p = fma2(p, q, K3); p = fma2(p, q, K2); \
        p = fma2(p, q, K1); p = fma2(p, q, K0);                     \
        ull u = fma2(z, p, KC);                                     \
        ull g = mul2(z, u);                                         \
        ull a2 = pk2((AD), (AD));                                   \
        (ACC) = fma2(a2, g, (ACC));                                 \
    } while (0)

    const int JC = NN / YD;          // 128 j per slice
    const int j0 = ty * JC;
    for (int j = j0; j < j0 + JC; j += 4) {
        ull cv2[4];
        #pragma unroll
        for (int u = 0; u < 4; ++u)
            cv2[u] = *reinterpret_cast<const ull*>(&g_cb[(j + u) * DD + d2]);
        #pragma unroll
        for (int ii = 0; ii < IPB; ++ii) {
            if (ii < rows) {
                float4 ad = *reinterpret_cast<const float4*>(
                    &adj[(size_t)(i0 + ii) * NN + j]);
                EVAL(acc[ii], av2[ii], cv2[0], ad.x);
                EVAL(acc[ii], av2[ii], cv2[1], ad.y);
                EVAL(acc[ii], av2[ii], cv2[2], ad.z);
                EVAL(acc[ii], av2[ii], cv2[3], ad.w);
            }
        }
    }
#undef EVAL

    __shared__ ull red[YD][IPB][64];
    #pragma unroll
    for (int ii = 0; ii < IPB; ++ii) red[ty][ii][t] = acc[ii];
    __syncthreads();
    if (ty < rows) {
        int ii = ty;
        ull s = red[0][ii][t];
        #pragma unroll
        for (int p = 1; p < YD; ++p) s = add2(s, red[p][ii][t]);
        *reinterpret_cast<ull*>(&g_agg[(i0 + ii) * DD + d2]) = s;
    }
}

// ====== kernel C: update+LN (+ a/c of next layer) fused, k-split ============
__global__ void k_upac(const float* __restrict__ Wu,
                       const float* __restrict__ bu,
                       const float* __restrict__ gamma,
                       const float* __restrict__ beta,
                       const float* __restrict__ Wm,
                       const float* __restrict__ bm,
                       int l, int do_next) {
    int i0 = blockIdx.x * ACR;
    int d  = threadIdx.x;
    int ty = threadIdx.y;
    int tid = ty * DD + d;

    __shared__ float hsh[ACR][DD], ash[ACR][DD], newh[ACR][DD];
    __shared__ float red[ACR][ACR][DD];
    __shared__ float rs_m[ACR][4], rs_v[ACR][4];

    {   // 512 threads load 512 elements of each
        int r = tid >> 7, c = tid & 127;
        hsh[r][c] = g_h  [(i0 + r) * DD + c];
        ash[r][c] = g_agg[(i0 + r) * DD + c];
    }
    __syncthreads();

    // ---- update GEMM: k-slice of 32 ----
    const float* W1 = Wu + (size_t)l * 2 * DD * DD;
    const float* W2 = W1 + DD * DD;
    {
        float acc[ACR] = {0.f, 0.f, 0.f, 0.f};
        int k0 = ty * 32;
        #pragma unroll 8
        for (int kk = 0; kk < 32; ++kk) {
            int k = k0 + kk;
            float w1 = W1[k * DD + d];
            float w2 = W2[k * DD + d];
            #pragma unroll
            for (int r = 0; r < ACR; ++r) {
                acc[r] = fmaf(hsh[r][k], w1, acc[r]);
                acc[r] = fmaf(ash[r][k], w2, acc[r]);
            }
        }
        #pragma unroll
        for (int r = 0; r < ACR; ++r) red[ty][r][d] = acc[r];
    }
    __syncthreads();

    // each ty finalizes row r = ty
    int r = ty;
    float x = bu[l * DD + d]
            + red[0][r][d] + red[1][r][d] + red[2][r][d] + red[3][r][d];
    x = gelu_exact(x) + hsh[r][d];

    // ---- layernorm (128 d-threads of this ty = 4 warps) ----
    float v = x;
    #pragma unroll
    for (int o = 16; o > 0; o >>= 1) v += __shfl_xor_sync(0xffffffffu, v, o);
    if ((d & 31) == 0) rs_m[r][d >> 5] = v;
    __syncthreads();
    float mean = (rs_m[r][0] + rs_m[r][1] + rs_m[r][2] + rs_m[r][3]) * (1.0f / DD);
    float xm = x - mean;
    float v2 = xm * xm;
    #pragma unroll
    for (int o = 16; o > 0; o >>= 1) v2 += __shfl_xor_sync(0xffffffffu, v2, o);
    if ((d & 31) == 0) rs_v[r][d >> 5] = v2;
    __syncthreads();
    float var = (rs_v[r][0] + rs_v[r][1] + rs_v[r][2] + rs_v[r][3]) * (1.0f / DD);
    float y = xm * rsqrtf(var + 1e-5f) * gamma[l * DD + d] + beta[l * DD + d];
    g_h[(i0 + r) * DD + d] = y;
    newh[r][d] = y;
    __syncthreads();

    // ---- a/c GEMM for layer l+1 ----
    if (do_next) {
        const float* WA = Wm + (size_t)(l + 1) * 2 * DD * DD;
        const float* WC = WA + DD * DD;
        float aa[ACR] = {0.f, 0.f, 0.f, 0.f};
        float cc[ACR] = {0.f, 0.f, 0.f, 0.f};
        int k0 = ty * 32;
        #pragma unroll 8
        for (int kk = 0; kk < 32; ++kk) {
            int k = k0 + kk;
            float wa = WA[k * DD + d];
            float wc = WC[k * DD + d];
            #pragma unroll
            for (int rr = 0; rr < ACR; ++rr) {
                float hv = newh[rr][k];
                aa[rr] = fmaf(hv, wa, aa[rr]);
                cc[rr] = fmaf(hv, wc, cc[rr]);
            }
        }
        #pragma unroll
        for (int rr = 0; rr < ACR; ++rr) red[ty][rr][d] = aa[rr];
        __syncthreads();
        g_a[(i0 + ty) * DD + d] =
            (red[0][ty][d] + red[1][ty][d] + red[2][ty][d] + red[3][ty][d]) * CSQ2;
        __syncthreads();
        #pragma unroll
        for (int rr = 0; rr < ACR; ++rr) red[ty][rr][d] = cc[rr];
        __syncthreads();
        g_cb[(i0 + ty) * DD + d] =
            (red[0][ty][d] + red[1][ty][d] + red[2][ty][d] + red[3][ty][d]
             + bm[(l + 1) * DD + d]) * CSQ2;
    }
}

// ---------------- kernel D: output heads ------------------------------------
// out layout: threat[1024] | intent[1024*5] | action[1024*5] | h[1024*128]
__global__ void k_heads(const float* __restrict__ Wt,
                        const float* __restrict__ bt,
                        const float* __restrict__ Wi,
                        const float* __restrict__ bi,
                        const float* __restrict__ Wa,
                        const float* __restrict__ ba,
                        float* __restrict__ out) {
    int i = blockIdx.x;
    int d = threadIdx.x;
    __shared__ float hsh[DD];
    float hv = g_h[i * DD + d];
    hsh[d] = hv;
    __syncthreads();

    out[NN + NN * 5 + NN * 5 + i * DD + d] = hv;   // h copy

    if (d < 5) {
        float s = bi[d];
        #pragma unroll 8
        for (int k = 0; k < DD; ++k) s = fmaf(hsh[k], Wi[k * 5 + d], s);
        out[NN + i * 5 + d] = s;
        float s2 = ba[d];
        #pragma unroll 8
        for (int k = 0; k < DD; ++k) s2 = fmaf(hsh[k], Wa[k * 5 + d], s2);
        out[NN + NN * 5 + i * 5 + d] = s2;
    }
    if (d == 5) {
        float s = bt[0];
        #pragma unroll 8
        for (int k = 0; k < DD; ++k) s = fmaf(hsh[k], Wt[k], s);
        out[i] = 5.0f / (1.0f + expf(-s));
    }
}

// ---------------- launcher ---------------------------------------------------
extern "C" void kernel_launch(void* const* d_in, const int* in_sizes, int n_in,
                              void* d_out, int out_size) {
    const float* nf    = (const float*)d_in[0];
    const float* adj   = (const float*)d_in[1];
    const float* Wp    = (const float*)d_in[2];
    const float* bp    = (const float*)d_in[3];
    const float* Wm    = (const float*)d_in[4];
    const float* bm    = (const float*)d_in[5];
    const float* Wu    = (const float*)d_in[6];
    const float* bu    = (const float*)d_in[7];
    const float* gamma = (const float*)d_in[8];
    const float* beta  = (const float*)d_in[9];
    const float* Wt    = (const float*)d_in[10];
    const float* bt    = (const float*)d_in[11];
    const float* Wi    = (const float*)d_in[12];
    const float* bi    = (const float*)d_in[13];
    const float* Wa    = (const float*)d_in[14];
    const float* ba    = (const float*)d_in[15];
    float* out = (float*)d_out;

    dim3 gblk(DD, ACR);
    k_proj_ac<<<NN / ACR, gblk>>>(nf, Wp, bp, Wm, bm);
    for (int l = 0; l < NL; ++l) {
        dim3 ablk(64, YD);
        k_agg<<<(NN + IPB - 1) / IPB, ablk>>>(adj);
        k_upac<<<NN / ACR, gblk>>>(Wu, bu, gamma, beta, Wm, bm, l, (l + 1 < NL) ? 1 : 0);
    }
    k_heads<<<NN, DD>>>(Wt, bt, Wi, bi, Wa, ba, out);
}